// round 5
// baseline (speedup 1.0000x reference)
#include <cuda_runtime.h>
#include <cuda_bf16.h>
#include <cstdint>

#define NE 16384
#define M_TOK 8192
#define NTILE 64
#define STAGES 4
#define BSTRIDE 272
#define ATILE (128 * BSTRIDE)   // 34816 bytes per fp8 tile (padded)

__device__ __align__(1024) uint8_t g_Xq[M_TOK * 256];   // tokens e4m3, token-major
__device__ __align__(1024) float   g_Xf[M_TOK * 256];   // tokens fp32, token-major
__device__ __align__(1024) uint8_t g_Cq[NE * 256];      // codebook e4m3
__device__ __align__(16)   float   g_cnorm[NE];
__device__ int g_cand[M_TOK * 32];
__device__ int g_idx[M_TOK];

static __device__ __forceinline__ uint32_t s2u(const void* p) {
    uint32_t a;
    asm("{ .reg .u64 t; cvta.to.shared.u64 t, %1; cvt.u32.u64 %0, t; }" : "=r"(a) : "l"(p));
    return a;
}
static __device__ __forceinline__ uint8_t f2e4m3(float v) {
    uint16_t u;
    asm("cvt.rn.satfinite.e4m3x2.f32 %0, %1, %2;" : "=h"(u) : "f"(v), "f"(v));
    return (uint8_t)(u & 0xFF);
}
#define CPA16(s, g) asm volatile("cp.async.cg.shared.global [%0], [%1], 16;" :: "r"(s), "l"(g) : "memory")
#define CPC()  asm volatile("cp.async.commit_group;" ::: "memory")
#define CPW2() asm volatile("cp.async.wait_group 2;" ::: "memory")

static __device__ __forceinline__ void ldsm4(uint32_t& r0, uint32_t& r1, uint32_t& r2,
                                             uint32_t& r3, uint32_t a) {
    asm volatile("ldmatrix.sync.aligned.m8n8.x4.shared.b16 {%0,%1,%2,%3}, [%4];"
                 : "=r"(r0), "=r"(r1), "=r"(r2), "=r"(r3) : "r"(a));
}
static __device__ __forceinline__ void mma_fp8(float& d0, float& d1, float& d2, float& d3,
                                               uint32_t a0, uint32_t a1, uint32_t a2,
                                               uint32_t a3, uint32_t b0, uint32_t b1) {
    asm volatile("mma.sync.aligned.m16n8k32.row.col.f32.e4m3.e4m3.f32 "
                 "{%0,%1,%2,%3}, {%4,%5,%6,%7}, {%8,%9}, {%0,%1,%2,%3};"
                 : "+f"(d0), "+f"(d1), "+f"(d2), "+f"(d3)
                 : "r"(a0), "r"(a1), "r"(a2), "r"(a3), "r"(b0), "r"(b1));
}

// ---------------- prep: transpose z -> token-major fp32 + e4m3 --------------
__global__ void conv_z_kernel(const float* __restrict__ z) {
    __shared__ float tile[32][33];
    int b = blockIdx.z, e0 = blockIdx.y * 32, p0 = blockIdx.x * 32;
    int tx = threadIdx.x, ty = threadIdx.y;
    const float* zb = z + (size_t)b * 256 * 1024;
#pragma unroll
    for (int r = 0; r < 4; r++)
        tile[ty + 8 * r][tx] = zb[(size_t)(e0 + ty + 8 * r) * 1024 + p0 + tx];
    __syncthreads();
#pragma unroll
    for (int r = 0; r < 4; r++) {
        int p = p0 + ty + 8 * r, e = e0 + tx;
        float v = tile[tx][ty + 8 * r];
        size_t o = (size_t)(b * 1024 + p) * 256 + e;
        g_Xf[o] = v;
        g_Xq[o] = f2e4m3(v);
    }
}

// ---------------- prep: codebook -> e4m3 + |c|^2 -----------------------------
__global__ void conv_cb_kernel(const float* __restrict__ cb) {
    int row = blockIdx.x * 8 + (threadIdx.x >> 5);
    int lane = threadIdx.x & 31;
    const float* r = cb + (size_t)row * 256;
    float s = 0.f;
#pragma unroll
    for (int i = 0; i < 8; i++) {
        float v = r[lane + 32 * i];
        s += v * v;
        g_Cq[(size_t)row * 256 + lane + 32 * i] = f2e4m3(v);
    }
#pragma unroll
    for (int o = 16; o > 0; o >>= 1) s += __shfl_down_sync(0xffffffffu, s, o);
    if (lane == 0) g_cnorm[row] = s;
}

// ---------------- main GEMM: mma.sync e4m3, top-2/slot + smem merge ----------
#define SM_CN 0                       // STAGES x 512 bytes
#define SM_A  2048
#define SM_B  (SM_A + ATILE)          // 36864
#define SMEMT (SM_B + STAGES * ATILE) // 176128

__global__ void __launch_bounds__(256, 1) vq_gemm_kernel() {
    extern __shared__ char smem[];
    const uint32_t sb = s2u(smem);
    const int tid  = threadIdx.x;
    const int lane = tid & 31;
    const int wid  = tid >> 5;
    const int wm   = wid >> 2;
    const int wn   = wid & 3;
    const int m0   = (blockIdx.x >> 1) * 128;
    const int half = blockIdx.x & 1;
    const int nb0  = half * (NE / 2);

    const char* gA = (const char*)g_Xq + (size_t)m0 * 256;
    const char* gB = (const char*)g_Cq + (size_t)nb0 * 256;
    const char* gC = (const char*)(g_cnorm + nb0);

    // cp.async mapping: 2048 16B chunks per 32KB tile; thread does 8
    const int c16  = (tid & 15) * 16;
    const int row0 = tid >> 4;   // + 16*i

    // ---- prologue: (A + B0 + cns0), (B1 + cns1), (B2 + cns2) ----
#pragma unroll
    for (int i = 0; i < 8; i++) {
        int r = row0 + 16 * i;
        CPA16(sb + SM_A + r * BSTRIDE + c16, gA + r * 256 + c16);
    }
#pragma unroll
    for (int i = 0; i < 8; i++) {
        int r = row0 + 16 * i;
        CPA16(sb + SM_B + r * BSTRIDE + c16, gB + r * 256 + c16);
    }
    if (tid < 32) CPA16(sb + SM_CN + tid * 16, gC + tid * 16);
    CPC();
#pragma unroll
    for (int st = 1; st <= 2; st++) {
#pragma unroll
        for (int i = 0; i < 8; i++) {
            int r = row0 + 16 * i;
            CPA16(sb + SM_B + st * ATILE + r * BSTRIDE + c16,
                  gB + st * 32768 + r * 256 + c16);
        }
        if (tid < 32) CPA16(sb + SM_CN + st * 512 + tid * 16, gC + st * 512 + tid * 16);
        CPC();
    }

    // ldmatrix bases
    uint32_t aBase[4];
#pragma unroll
    for (int mi = 0; mi < 4; mi++)
        aBase[mi] = sb + SM_A + (wm * 64 + mi * 16 + (lane & 15)) * BSTRIDE + (lane >> 4) * 16;
    const uint32_t bRowOff =
        (uint32_t)((wn * 32 + ((lane >> 4) & 1) * 8 + (lane & 7)) * BSTRIDE + ((lane >> 3) & 1) * 16);

    // top-2 per (thread, row-slot) over this thread's 512-code slices
    float tv0[8], tv1[8];
    int   ti0[8], ti1[8];
#pragma unroll
    for (int i = 0; i < 8; i++) { tv0[i] = 3.4e38f; tv1[i] = 3.4e38f; ti0[i] = 0; ti1[i] = 0; }

#pragma unroll 1
    for (int t = 0; t < NTILE; t++) {
        const int st = t & 3;
        CPW2();
        __syncthreads();

        float acc[4][4][4];
#pragma unroll
        for (int mi = 0; mi < 4; mi++)
#pragma unroll
            for (int ni = 0; ni < 4; ni++)
#pragma unroll
                for (int q = 0; q < 4; q++) acc[mi][ni][q] = 0.f;

        const uint32_t bBuf = sb + SM_B + st * ATILE + bRowOff;
#pragma unroll
        for (int ks = 0; ks < 8; ks++) {
            uint32_t a[4][4];
#pragma unroll
            for (int mi = 0; mi < 4; mi++)
                ldsm4(a[mi][0], a[mi][1], a[mi][2], a[mi][3], aBase[mi] + ks * 32);
            uint32_t b[4][2];
#pragma unroll
            for (int nb = 0; nb < 2; nb++) {
                uint32_t r0, r1, r2, r3;
                ldsm4(r0, r1, r2, r3, bBuf + nb * (16 * BSTRIDE) + ks * 32);
                b[nb * 2][0] = r0;     b[nb * 2][1] = r1;
                b[nb * 2 + 1][0] = r2; b[nb * 2 + 1][1] = r3;
            }
#pragma unroll
            for (int mi = 0; mi < 4; mi++)
#pragma unroll
                for (int ni = 0; ni < 4; ni++)
                    mma_fp8(acc[mi][ni][0], acc[mi][ni][1], acc[mi][ni][2], acc[mi][ni][3],
                            a[mi][0], a[mi][1], a[mi][2], a[mi][3], b[ni][0], b[ni][1]);
        }

        // score + top-2 per slot (ascending n; strict < keeps lowest index)
        const float2* cns2 = (const float2*)(smem + SM_CN + st * 512);
        const int nbase = nb0 + t * 128;
#pragma unroll
        for (int ni = 0; ni < 4; ni++) {
            float2 cn = cns2[wn * 16 + ni * 4 + (lane & 3)];
            int ncol = nbase + wn * 32 + ni * 8 + (lane & 3) * 2;
#pragma unroll
            for (int mi = 0; mi < 4; mi++) {
#pragma unroll
                for (int hi = 0; hi < 2; hi++) {
                    const int sl = mi * 2 + hi;
                    float s0 = fmaf(-2.f, acc[mi][ni][hi * 2 + 0], cn.x);
                    float s1 = fmaf(-2.f, acc[mi][ni][hi * 2 + 1], cn.y);
                    if (s0 < tv1[sl]) {
                        if (s0 < tv0[sl]) { tv1[sl]=tv0[sl]; ti1[sl]=ti0[sl]; tv0[sl]=s0; ti0[sl]=ncol; }
                        else              { tv1[sl]=s0; ti1[sl]=ncol; }
                    }
                    if (s1 < tv1[sl]) {
                        if (s1 < tv0[sl]) { tv1[sl]=tv0[sl]; ti1[sl]=ti0[sl]; tv0[sl]=s1; ti0[sl]=ncol+1; }
                        else              { tv1[sl]=s1; ti1[sl]=ncol+1; }
                    }
                }
            }
        }

        __syncthreads();
        if (t + 3 < NTILE) {
            const int ds = (t + 3) & 3;
            const char* src = gB + (size_t)(t + 3) * 32768;
#pragma unroll
            for (int i = 0; i < 8; i++) {
                int r = row0 + 16 * i;
                CPA16(sb + SM_B + ds * ATILE + r * BSTRIDE + c16, src + r * 256 + c16);
            }
            if (tid < 32)
                CPA16(sb + SM_CN + ds * 512 + tid * 16, gC + (size_t)(t + 3) * 512 + tid * 16);
        }
        CPC();   // uniform group count (empty groups near the tail)
    }

    // ---- merge: 8 entries per (row, wn) -> top-4 of the 2048-code slice ----
    float* sval = (float*)(smem + SM_B);
    int*   sidx = (int*)(smem + SM_B + 16384);
    __syncthreads();
#pragma unroll
    for (int mi = 0; mi < 4; mi++)
#pragma unroll
        for (int hi = 0; hi < 2; hi++) {
            const int sl = mi * 2 + hi;
            int row = wm * 64 + mi * 16 + (lane >> 2) + hi * 8;
            int g = row * 4 + wn;
            int e = (lane & 3) * 2;
            sval[g * 8 + e]     = tv0[sl];  sidx[g * 8 + e]     = ti0[sl];
            sval[g * 8 + e + 1] = tv1[sl];  sidx[g * 8 + e + 1] = ti1[sl];
        }
    __syncthreads();
#pragma unroll
    for (int gg = 0; gg < 2; gg++) {
        int g = tid + gg * 256;
        float v[8]; int id[8];
#pragma unroll
        for (int e = 0; e < 8; e++) { v[e] = sval[g * 8 + e]; id[e] = sidx[g * 8 + e]; }
        int row = g >> 2, wn_ = g & 3;
        int* oc = g_cand + (size_t)(m0 + row) * 32 + half * 16 + wn_ * 4;
#pragma unroll
        for (int j = 0; j < 4; j++) {
            int bm = 0;
#pragma unroll
            for (int e = 1; e < 8; e++)
                if (v[e] < v[bm] || (v[e] == v[bm] && id[e] < id[bm])) bm = e;
            oc[j] = id[bm];
            v[bm] = 3.5e38f;
        }
    }
}

// ---------------- exact fp32 rescore of 32 candidates per token --------------
__global__ void rescore_kernel(const float* __restrict__ cb) {
    int t = blockIdx.x * 8 + (threadIdx.x >> 5);
    int lane = threadIdx.x & 31;
    const float* x = g_Xf + (size_t)t * 256;
    float xv[8];
#pragma unroll
    for (int i = 0; i < 8; i++) xv[i] = x[lane + 32 * i];
    float best = 3.4e38f;
    int bi = NE;
#pragma unroll 1
    for (int c = 0; c < 32; c++) {
        int n = g_cand[(size_t)t * 32 + c];
        const float* cr = cb + (size_t)n * 256;
        float d = 0.f;
#pragma unroll
        for (int i = 0; i < 8; i++) d = fmaf(xv[i], cr[lane + 32 * i], d);
#pragma unroll
        for (int o = 16; o > 0; o >>= 1) d += __shfl_xor_sync(0xffffffffu, d, o);
        float sc = fmaf(-2.f, d, g_cnorm[n]);
        if (sc < best || (sc == best && n < bi)) { best = sc; bi = n; }
    }
    if (lane == 0) g_idx[t] = bi;
}

// ---------------- gather: out[b,e,h,w] = cb[idx[b,h,w], e] -------------------
__global__ void gather_kernel(const float* __restrict__ cb, float* __restrict__ out) {
    int bh = blockIdx.x;
    int b = bh >> 5, h = bh & 31;
    int w = threadIdx.x & 31, e0 = threadIdx.x >> 5;
    int t = b * 1024 + h * 32 + w;
    int idx = g_idx[t];
    const float* row = cb + (size_t)idx * 256;
    float* ob = out + (size_t)b * (256 * 1024) + h * 32 + w;
#pragma unroll
    for (int e = e0; e < 256; e += 8) ob[e * 1024] = row[e];
}

extern "C" void kernel_launch(void* const* d_in, const int* in_sizes, int n_in,
                              void* d_out, int out_size) {
    const float* z  = (const float*)d_in[0];
    const float* cb = (const float*)d_in[1];
    float* out = (float*)d_out;

    static int cfg_done = 0;
    if (!cfg_done) {
        cudaFuncSetAttribute(vq_gemm_kernel, cudaFuncAttributeMaxDynamicSharedMemorySize, SMEMT);
        cfg_done = 1;
    }

    conv_z_kernel<<<dim3(32, 8, 8), dim3(32, 8)>>>(z);
    conv_cb_kernel<<<NE / 8, 256>>>(cb);
    vq_gemm_kernel<<<128, 256, SMEMT>>>();
    rescore_kernel<<<M_TOK / 8, 256>>>(cb);
    gather_kernel<<<256, 256>>>(cb, out);
}

// round 6
// speedup vs baseline: 1.1324x; 1.1324x over previous
#include <cuda_runtime.h>
#include <cuda_bf16.h>
#include <cstdint>

#define NE 16384
#define M_TOK 8192
#define BSTRIDE 528
#define BTILE (128 * BSTRIDE)      // 67584 bytes per bf16 tile (padded)

__device__ __align__(1024) __nv_bfloat16 g_Xb[M_TOK * 256];
__device__ __align__(1024) float         g_Xf[M_TOK * 256];
__device__ __align__(1024) __nv_bfloat16 g_Cb[NE * 256];
__device__ __align__(16)   float         g_cnorm[NE];
__device__ int g_cand[M_TOK * 32];
__device__ int g_idx[M_TOK];

static __device__ __forceinline__ uint32_t s2u(const void* p) {
    uint32_t a;
    asm("{ .reg .u64 t; cvta.to.shared.u64 t, %1; cvt.u32.u64 %0, t; }" : "=r"(a) : "l"(p));
    return a;
}
#define CPA16(s, g) asm volatile("cp.async.cg.shared.global [%0], [%1], 16;" :: "r"(s), "l"(g) : "memory")
#define CPC()  asm volatile("cp.async.commit_group;" ::: "memory")
#define CPW1() asm volatile("cp.async.wait_group 1;" ::: "memory")
#define CPW0() asm volatile("cp.async.wait_group 0;" ::: "memory")

static __device__ __forceinline__ void ldsm4(uint32_t& r0, uint32_t& r1, uint32_t& r2,
                                             uint32_t& r3, uint32_t a) {
    asm volatile("ldmatrix.sync.aligned.m8n8.x4.shared.b16 {%0,%1,%2,%3}, [%4];"
                 : "=r"(r0), "=r"(r1), "=r"(r2), "=r"(r3) : "r"(a));
}
static __device__ __forceinline__ void mma16816(float& d0, float& d1, float& d2, float& d3,
                                                uint32_t a0, uint32_t a1, uint32_t a2,
                                                uint32_t a3, uint32_t b0, uint32_t b1) {
    asm volatile("mma.sync.aligned.m16n8k16.row.col.f32.bf16.bf16.f32 "
                 "{%0,%1,%2,%3}, {%4,%5,%6,%7}, {%8,%9}, {%0,%1,%2,%3};"
                 : "+f"(d0), "+f"(d1), "+f"(d2), "+f"(d3)
                 : "r"(a0), "r"(a1), "r"(a2), "r"(a3), "r"(b0), "r"(b1));
}

// ---------------- prep: transpose z -> token-major fp32 + bf16 --------------
__global__ void conv_z_kernel(const float* __restrict__ z) {
    __shared__ float tile[32][33];
    int b = blockIdx.z, e0 = blockIdx.y * 32, p0 = blockIdx.x * 32;
    int tx = threadIdx.x, ty = threadIdx.y;
    const float* zb = z + (size_t)b * 256 * 1024;
#pragma unroll
    for (int r = 0; r < 4; r++)
        tile[ty + 8 * r][tx] = zb[(size_t)(e0 + ty + 8 * r) * 1024 + p0 + tx];
    __syncthreads();
#pragma unroll
    for (int r = 0; r < 4; r++) {
        int p = p0 + ty + 8 * r, e = e0 + tx;
        float v = tile[tx][ty + 8 * r];
        size_t o = (size_t)(b * 1024 + p) * 256 + e;
        g_Xf[o] = v;
        g_Xb[o] = __float2bfloat16(v);
    }
}

// ---------------- prep: codebook -> bf16 + |c|^2 -----------------------------
__global__ void conv_cb_kernel(const float* __restrict__ cb) {
    int row = blockIdx.x * 8 + (threadIdx.x >> 5);
    int lane = threadIdx.x & 31;
    const float* r = cb + (size_t)row * 256;
    float s = 0.f;
#pragma unroll
    for (int i = 0; i < 8; i++) {
        float v = r[lane + 32 * i];
        s += v * v;
        g_Cb[(size_t)row * 256 + lane + 32 * i] = __float2bfloat16(v);
    }
#pragma unroll
    for (int o = 16; o > 0; o >>= 1) s += __shfl_down_sync(0xffffffffu, s, o);
    if (lane == 0) g_cnorm[row] = s;
}

// ---------------- main GEMM: 1024 jobs = 64 m-tiles x 16 n-chunks -----------
// smem: cns 4KB @0, A @4096 (67584), B[2] @71680
#define SM_CN 0
#define SM_A  4096
#define SM_B  71680
#define SMEMT (71680 + 2 * BTILE)   // 206848

__global__ void __launch_bounds__(256, 1) vq_gemm_kernel() {
    extern __shared__ char smem[];
    const uint32_t sb = s2u(smem);
    const int tid  = threadIdx.x;
    const int lane = tid & 31;
    const int wid  = tid >> 5;
    const int wm   = wid >> 2;            // 0..1
    const int wn   = wid & 3;             // 0..3
    const int m0    = (blockIdx.x & 63) * 128;   // in-wave CTAs share chunk -> B in L2
    const int chunk = blockIdx.x >> 6;           // 0..15
    const int nb0   = chunk * 1024;

    const char* gA = (const char*)g_Xb + (size_t)m0 * 512;
    const char* gB = (const char*)g_Cb + (size_t)nb0 * 512;

    const int c16  = (tid & 31) * 16;
    const int row0 = tid >> 5;

    // ---- prologue: group0 = A + B0 + all cns(4KB); group1 = B1 ----
#pragma unroll
    for (int i = 0; i < 16; i++) {
        int r = row0 + 8 * i;
        CPA16(sb + SM_A + r * BSTRIDE + c16, gA + r * 512 + c16);
    }
#pragma unroll
    for (int i = 0; i < 16; i++) {
        int r = row0 + 8 * i;
        CPA16(sb + SM_B + r * BSTRIDE + c16, gB + r * 512 + c16);
    }
    CPA16(sb + SM_CN + tid * 16, (const char*)(g_cnorm + nb0) + tid * 16);
    CPC();
#pragma unroll
    for (int i = 0; i < 16; i++) {
        int r = row0 + 8 * i;
        CPA16(sb + SM_B + BTILE + r * BSTRIDE + c16, gB + 65536 + r * 512 + c16);
    }
    CPC();

    uint32_t aBase[4];
#pragma unroll
    for (int mi = 0; mi < 4; mi++)
        aBase[mi] = sb + SM_A + (wm * 64 + mi * 16 + (lane & 15)) * BSTRIDE + (lane >> 4) * 16;
    const uint32_t bRowOff =
        (uint32_t)((wn * 32 + ((lane >> 4) & 1) * 8 + (lane & 7)) * BSTRIDE + ((lane >> 3) & 1) * 16);

    float tv0[8], tv1[8];
    int   ti0[8], ti1[8];
#pragma unroll
    for (int i = 0; i < 8; i++) { tv0[i] = 3.4e38f; tv1[i] = 3.4e38f; ti0[i] = 0; ti1[i] = 0; }

#pragma unroll 1
    for (int t = 0; t < 8; t++) {
        const int s = t & 1;
        if (t < 7) CPW1(); else CPW0();
        __syncthreads();

        float acc[4][4][4];
#pragma unroll
        for (int mi = 0; mi < 4; mi++)
#pragma unroll
            for (int ni = 0; ni < 4; ni++)
#pragma unroll
                for (int q = 0; q < 4; q++) acc[mi][ni][q] = 0.f;

        const uint32_t bBuf = sb + SM_B + s * BTILE + bRowOff;
#pragma unroll
        for (int ks = 0; ks < 16; ks++) {
            uint32_t a[4][4];
#pragma unroll
            for (int mi = 0; mi < 4; mi++)
                ldsm4(a[mi][0], a[mi][1], a[mi][2], a[mi][3], aBase[mi] + ks * 32);
            uint32_t b[4][2];
#pragma unroll
            for (int nb = 0; nb < 2; nb++) {
                uint32_t r0, r1, r2, r3;
                ldsm4(r0, r1, r2, r3, bBuf + nb * (16 * BSTRIDE) + ks * 32);
                b[nb * 2][0] = r0;     b[nb * 2][1] = r1;
                b[nb * 2 + 1][0] = r2; b[nb * 2 + 1][1] = r3;
            }
#pragma unroll
            for (int mi = 0; mi < 4; mi++)
#pragma unroll
                for (int ni = 0; ni < 4; ni++)
                    mma16816(acc[mi][ni][0], acc[mi][ni][1], acc[mi][ni][2], acc[mi][ni][3],
                             a[mi][0], a[mi][1], a[mi][2], a[mi][3], b[ni][0], b[ni][1]);
        }

        // score + per-slot top-2 (ascending n; strict < keeps lowest index)
        const float2* cns2 = (const float2*)(smem + SM_CN + t * 512);
        const int nbase = nb0 + t * 128;
#pragma unroll
        for (int ni = 0; ni < 4; ni++) {
            float2 cn = cns2[wn * 16 + ni * 4 + (lane & 3)];
            int ncol = nbase + wn * 32 + ni * 8 + (lane & 3) * 2;
#pragma unroll
            for (int mi = 0; mi < 4; mi++) {
#pragma unroll
                for (int hi = 0; hi < 2; hi++) {
                    const int sl = mi * 2 + hi;
                    float s0 = fmaf(-2.f, acc[mi][ni][hi * 2 + 0], cn.x);
                    float s1 = fmaf(-2.f, acc[mi][ni][hi * 2 + 1], cn.y);
                    if (s0 < tv1[sl]) {
                        if (s0 < tv0[sl]) { tv1[sl]=tv0[sl]; ti1[sl]=ti0[sl]; tv0[sl]=s0; ti0[sl]=ncol; }
                        else              { tv1[sl]=s0; ti1[sl]=ncol; }
                    }
                    if (s1 < tv1[sl]) {
                        if (s1 < tv0[sl]) { tv1[sl]=tv0[sl]; ti1[sl]=ti0[sl]; tv0[sl]=s1; ti0[sl]=ncol+1; }
                        else              { tv1[sl]=s1; ti1[sl]=ncol+1; }
                    }
                }
            }
        }

        __syncthreads();   // all reads of stage s done before overwrite
        if (t + 2 < 8) {
            const char* src = gB + (size_t)(t + 2) * 65536;
#pragma unroll
            for (int i = 0; i < 16; i++) {
                int r = row0 + 8 * i;
                CPA16(sb + SM_B + s * BTILE + r * BSTRIDE + c16, src + r * 512 + c16);
            }
        }
        CPC();   // uniform group count
    }

    // ---- merge: 32 entries per row -> top-2 of the 1024-code chunk ----
    float* sval = (float*)(smem + SM_B);             // 128 rows x 32 floats = 16KB
    int*   sidx = (int*)(smem + SM_B + 16384);
    __syncthreads();
#pragma unroll
    for (int mi = 0; mi < 4; mi++)
#pragma unroll
        for (int hi = 0; hi < 2; hi++) {
            const int sl = mi * 2 + hi;
            int row = wm * 64 + mi * 16 + (lane >> 2) + hi * 8;
            int e = wn * 8 + (lane & 3) * 2;
            sval[row * 32 + e]     = tv0[sl];  sidx[row * 32 + e]     = ti0[sl];
            sval[row * 32 + e + 1] = tv1[sl];  sidx[row * 32 + e + 1] = ti1[sl];
        }
    __syncthreads();
    if (tid < 128) {
        const float* v = sval + tid * 32;
        const int*   id = sidx + tid * 32;
        float b0 = 3.4e38f, b1 = 3.4e38f;
        int   j0 = NE, j1 = NE;
#pragma unroll
        for (int e = 0; e < 32; e++) {
            float vv = v[e]; int ii = id[e];
            bool lt0 = (vv < b0) || (vv == b0 && ii < j0);
            bool lt1 = (vv < b1) || (vv == b1 && ii < j1);
            if (lt0)      { b1 = b0; j1 = j0; b0 = vv; j0 = ii; }
            else if (lt1) { b1 = vv; j1 = ii; }
        }
        int* oc = g_cand + (size_t)(m0 + tid) * 32 + chunk * 2;
        oc[0] = j0; oc[1] = j1;
    }
}

// ---------------- exact fp32 rescore of 32 candidates per token --------------
__global__ void rescore_kernel(const float* __restrict__ cb) {
    int t = blockIdx.x * 8 + (threadIdx.x >> 5);
    int lane = threadIdx.x & 31;
    const float* x = g_Xf + (size_t)t * 256;
    float xv[8];
#pragma unroll
    for (int i = 0; i < 8; i++) xv[i] = x[lane + 32 * i];
    float best = 3.4e38f;
    int bi = NE;
#pragma unroll 1
    for (int c = 0; c < 32; c++) {
        int n = g_cand[(size_t)t * 32 + c];
        const float* cr = cb + (size_t)n * 256;
        float d = 0.f;
#pragma unroll
        for (int i = 0; i < 8; i++) d = fmaf(xv[i], cr[lane + 32 * i], d);
#pragma unroll
        for (int o = 16; o > 0; o >>= 1) d += __shfl_xor_sync(0xffffffffu, d, o);
        float sc = fmaf(-2.f, d, g_cnorm[n]);
        if (sc < best || (sc == best && n < bi)) { best = sc; bi = n; }
    }
    if (lane == 0) g_idx[t] = bi;
}

// ---------------- gather: out[b,e,h,w] = cb[idx[b,h,w], e] -------------------
__global__ void gather_kernel(const float* __restrict__ cb, float* __restrict__ out) {
    int bh = blockIdx.x;
    int b = bh >> 5, h = bh & 31;
    int w = threadIdx.x & 31, e0 = threadIdx.x >> 5;
    int t = b * 1024 + h * 32 + w;
    int idx = g_idx[t];
    const float* row = cb + (size_t)idx * 256;
    float* ob = out + (size_t)b * (256 * 1024) + h * 32 + w;
#pragma unroll
    for (int e = e0; e < 256; e += 8) ob[e * 1024] = row[e];
}

extern "C" void kernel_launch(void* const* d_in, const int* in_sizes, int n_in,
                              void* d_out, int out_size) {
    const float* z  = (const float*)d_in[0];
    const float* cb = (const float*)d_in[1];
    float* out = (float*)d_out;

    static int cfg_done = 0;
    if (!cfg_done) {
        cudaFuncSetAttribute(vq_gemm_kernel, cudaFuncAttributeMaxDynamicSharedMemorySize, SMEMT);
        cfg_done = 1;
    }

    conv_z_kernel<<<dim3(32, 8, 8), dim3(32, 8)>>>(z);
    conv_cb_kernel<<<NE / 8, 256>>>(cb);
    vq_gemm_kernel<<<1024, 256, SMEMT>>>();
    rescore_kernel<<<M_TOK / 8, 256>>>(cb);
    gather_kernel<<<256, 256>>>(cb, out);
}

// round 7
// speedup vs baseline: 1.1365x; 1.0036x over previous
#include <cuda_runtime.h>
#include <cuda_bf16.h>
#include <cstdint>

#define NE 16384
#define M_TOK 8192
#define BSTRIDE 528
#define BTILE (128 * BSTRIDE)      // 67584 bytes per bf16 tile (padded)

__device__ __align__(1024) __nv_bfloat16 g_Xb[M_TOK * 256];
__device__ __align__(1024) float         g_Xf[M_TOK * 256];
__device__ __align__(1024) __nv_bfloat16 g_Cb[NE * 256];
__device__ __align__(16)   float         g_cnorm[NE];
__device__ int g_cand[M_TOK * 32];
__device__ int g_idx[M_TOK];

static __device__ __forceinline__ uint32_t s2u(const void* p) {
    uint32_t a;
    asm("{ .reg .u64 t; cvta.to.shared.u64 t, %1; cvt.u32.u64 %0, t; }" : "=r"(a) : "l"(p));
    return a;
}
#define CPA16(s, g) asm volatile("cp.async.cg.shared.global [%0], [%1], 16;" :: "r"(s), "l"(g) : "memory")
#define CPC()  asm volatile("cp.async.commit_group;" ::: "memory")
#define CPW1() asm volatile("cp.async.wait_group 1;" ::: "memory")
#define CPW0() asm volatile("cp.async.wait_group 0;" ::: "memory")

static __device__ __forceinline__ void ldsm4(uint32_t& r0, uint32_t& r1, uint32_t& r2,
                                             uint32_t& r3, uint32_t a) {
    asm volatile("ldmatrix.sync.aligned.m8n8.x4.shared.b16 {%0,%1,%2,%3}, [%4];"
                 : "=r"(r0), "=r"(r1), "=r"(r2), "=r"(r3) : "r"(a));
}
static __device__ __forceinline__ void mma16816(float& d0, float& d1, float& d2, float& d3,
                                                uint32_t a0, uint32_t a1, uint32_t a2,
                                                uint32_t a3, uint32_t b0, uint32_t b1) {
    asm volatile("mma.sync.aligned.m16n8k16.row.col.f32.bf16.bf16.f32 "
                 "{%0,%1,%2,%3}, {%4,%5,%6,%7}, {%8,%9}, {%0,%1,%2,%3};"
                 : "+f"(d0), "+f"(d1), "+f"(d2), "+f"(d3)
                 : "r"(a0), "r"(a1), "r"(a2), "r"(a3), "r"(b0), "r"(b1));
}

// ---------------- prep: transpose z -> token-major fp32 + bf16 --------------
__global__ void conv_z_kernel(const float* __restrict__ z) {
    __shared__ float tile[32][33];
    int b = blockIdx.z, e0 = blockIdx.y * 32, p0 = blockIdx.x * 32;
    int tx = threadIdx.x, ty = threadIdx.y;
    const float* zb = z + (size_t)b * 256 * 1024;
#pragma unroll
    for (int r = 0; r < 4; r++)
        tile[ty + 8 * r][tx] = zb[(size_t)(e0 + ty + 8 * r) * 1024 + p0 + tx];
    __syncthreads();
#pragma unroll
    for (int r = 0; r < 4; r++) {
        int p = p0 + ty + 8 * r, e = e0 + tx;
        float v = tile[tx][ty + 8 * r];
        size_t o = (size_t)(b * 1024 + p) * 256 + e;
        g_Xf[o] = v;
        g_Xb[o] = __float2bfloat16(v);
    }
}

// ---------------- prep: codebook -> bf16 + |c|^2 -----------------------------
__global__ void conv_cb_kernel(const float* __restrict__ cb) {
    int row = blockIdx.x * 8 + (threadIdx.x >> 5);
    int lane = threadIdx.x & 31;
    const float* r = cb + (size_t)row * 256;
    float s = 0.f;
#pragma unroll
    for (int i = 0; i < 8; i++) {
        float v = r[lane + 32 * i];
        s += v * v;
        g_Cb[(size_t)row * 256 + lane + 32 * i] = __float2bfloat16(v);
    }
#pragma unroll
    for (int o = 16; o > 0; o >>= 1) s += __shfl_down_sync(0xffffffffu, s, o);
    if (lane == 0) g_cnorm[row] = s;
}

// ---------------- main GEMM: 1024 jobs = 64 m-tiles x 16 n-chunks -----------
// smem: cns 4KB @0, A @4096 (67584), B[2] @71680
#define SM_CN 0
#define SM_A  4096
#define SM_B  71680
#define SMEMT (71680 + 2 * BTILE)   // 206848

__global__ void __launch_bounds__(256, 1) vq_gemm_kernel() {
    extern __shared__ char smem[];
    const uint32_t sb = s2u(smem);
    const int tid  = threadIdx.x;
    const int lane = tid & 31;
    const int wid  = tid >> 5;
    const int wm   = wid >> 2;            // 0..1
    const int wn   = wid & 3;             // 0..3
    const int m0    = (blockIdx.x & 63) * 128;   // in-wave CTAs share chunk -> B in L2
    const int chunk = blockIdx.x >> 6;           // 0..15
    const int nb0   = chunk * 1024;

    const char* gA = (const char*)g_Xb + (size_t)m0 * 512;
    const char* gB = (const char*)g_Cb + (size_t)nb0 * 512;

    const int c16  = (tid & 31) * 16;
    const int row0 = tid >> 5;

    // ---- prologue: group0 = A + B0 + all cns(4KB); group1 = B1 ----
#pragma unroll
    for (int i = 0; i < 16; i++) {
        int r = row0 + 8 * i;
        CPA16(sb + SM_A + r * BSTRIDE + c16, gA + r * 512 + c16);
    }
#pragma unroll
    for (int i = 0; i < 16; i++) {
        int r = row0 + 8 * i;
        CPA16(sb + SM_B + r * BSTRIDE + c16, gB + r * 512 + c16);
    }
    CPA16(sb + SM_CN + tid * 16, (const char*)(g_cnorm + nb0) + tid * 16);
    CPC();
#pragma unroll
    for (int i = 0; i < 16; i++) {
        int r = row0 + 8 * i;
        CPA16(sb + SM_B + BTILE + r * BSTRIDE + c16, gB + 65536 + r * 512 + c16);
    }
    CPC();

    uint32_t aBase[4];
#pragma unroll
    for (int mi = 0; mi < 4; mi++)
        aBase[mi] = sb + SM_A + (wm * 64 + mi * 16 + (lane & 15)) * BSTRIDE + (lane >> 4) * 16;
    const uint32_t bRowOff =
        (uint32_t)((wn * 32 + ((lane >> 4) & 1) * 8 + (lane & 7)) * BSTRIDE + ((lane >> 3) & 1) * 16);

    float tv0[8], tv1[8];
    int   ti0[8], ti1[8];
#pragma unroll
    for (int i = 0; i < 8; i++) { tv0[i] = 3.4e38f; tv1[i] = 3.4e38f; ti0[i] = 0; ti1[i] = 0; }

#pragma unroll 1
    for (int t = 0; t < 8; t++) {
        const int s = t & 1;
        if (t < 7) CPW1(); else CPW0();
        __syncthreads();

        float acc[4][4][4];
#pragma unroll
        for (int mi = 0; mi < 4; mi++)
#pragma unroll
            for (int ni = 0; ni < 4; ni++)
#pragma unroll
                for (int q = 0; q < 4; q++) acc[mi][ni][q] = 0.f;

        const uint32_t bBuf = sb + SM_B + s * BTILE + bRowOff;
#pragma unroll
        for (int ks = 0; ks < 16; ks++) {
            uint32_t a[4][4];
#pragma unroll
            for (int mi = 0; mi < 4; mi++)
                ldsm4(a[mi][0], a[mi][1], a[mi][2], a[mi][3], aBase[mi] + ks * 32);
            uint32_t b[4][2];
#pragma unroll
            for (int nb = 0; nb < 2; nb++) {
                uint32_t r0, r1, r2, r3;
                ldsm4(r0, r1, r2, r3, bBuf + nb * (16 * BSTRIDE) + ks * 32);
                b[nb * 2][0] = r0;     b[nb * 2][1] = r1;
                b[nb * 2 + 1][0] = r2; b[nb * 2 + 1][1] = r3;
            }
#pragma unroll
            for (int mi = 0; mi < 4; mi++)
#pragma unroll
                for (int ni = 0; ni < 4; ni++)
                    mma16816(acc[mi][ni][0], acc[mi][ni][1], acc[mi][ni][2], acc[mi][ni][3],
                             a[mi][0], a[mi][1], a[mi][2], a[mi][3], b[ni][0], b[ni][1]);
        }

        // score + per-slot top-2 (ascending n; strict < keeps lowest index)
        const float2* cns2 = (const float2*)(smem + SM_CN + t * 512);
        const int nbase = nb0 + t * 128;
#pragma unroll
        for (int ni = 0; ni < 4; ni++) {
            float2 cn = cns2[wn * 16 + ni * 4 + (lane & 3)];
            int ncol = nbase + wn * 32 + ni * 8 + (lane & 3) * 2;
#pragma unroll
            for (int mi = 0; mi < 4; mi++) {
#pragma unroll
                for (int hi = 0; hi < 2; hi++) {
                    const int sl = mi * 2 + hi;
                    float s0 = fmaf(-2.f, acc[mi][ni][hi * 2 + 0], cn.x);
                    float s1 = fmaf(-2.f, acc[mi][ni][hi * 2 + 1], cn.y);
                    if (s0 < tv1[sl]) {
                        if (s0 < tv0[sl]) { tv1[sl]=tv0[sl]; ti1[sl]=ti0[sl]; tv0[sl]=s0; ti0[sl]=ncol; }
                        else              { tv1[sl]=s0; ti1[sl]=ncol; }
                    }
                    if (s1 < tv1[sl]) {
                        if (s1 < tv0[sl]) { tv1[sl]=tv0[sl]; ti1[sl]=ti0[sl]; tv0[sl]=s1; ti0[sl]=ncol+1; }
                        else              { tv1[sl]=s1; ti1[sl]=ncol+1; }
                    }
                }
            }
        }

        __syncthreads();   // all reads of stage s done before overwrite
        if (t + 2 < 8) {
            const char* src = gB + (size_t)(t + 2) * 65536;
#pragma unroll
            for (int i = 0; i < 16; i++) {
                int r = row0 + 8 * i;
                CPA16(sb + SM_B + s * BTILE + r * BSTRIDE + c16, src + r * 512 + c16);
            }
        }
        CPC();   // uniform group count
    }

    // ---- merge: 32 entries per row -> top-2 of the 1024-code chunk ----
    float* sval = (float*)(smem + SM_B);             // 128 rows x 32 floats = 16KB
    int*   sidx = (int*)(smem + SM_B + 16384);
    __syncthreads();
#pragma unroll
    for (int mi = 0; mi < 4; mi++)
#pragma unroll
        for (int hi = 0; hi < 2; hi++) {
            const int sl = mi * 2 + hi;
            int row = wm * 64 + mi * 16 + (lane >> 2) + hi * 8;
            int e = wn * 8 + (lane & 3) * 2;
            sval[row * 32 + e]     = tv0[sl];  sidx[row * 32 + e]     = ti0[sl];
            sval[row * 32 + e + 1] = tv1[sl];  sidx[row * 32 + e + 1] = ti1[sl];
        }
    __syncthreads();
    if (tid < 128) {
        const float* v = sval + tid * 32;
        const int*   id = sidx + tid * 32;
        float b0 = 3.4e38f, b1 = 3.4e38f;
        int   j0 = NE, j1 = NE;
#pragma unroll
        for (int e = 0; e < 32; e++) {
            float vv = v[e]; int ii = id[e];
            bool lt0 = (vv < b0) || (vv == b0 && ii < j0);
            bool lt1 = (vv < b1) || (vv == b1 && ii < j1);
            if (lt0)      { b1 = b0; j1 = j0; b0 = vv; j0 = ii; }
            else if (lt1) { b1 = vv; j1 = ii; }
        }
        int* oc = g_cand + (size_t)(m0 + tid) * 32 + chunk * 2;
        oc[0] = j0; oc[1] = j1;
    }
}

// ---------------- exact fp32 rescore of 32 candidates per token --------------
__global__ void rescore_kernel(const float* __restrict__ cb) {
    int t = blockIdx.x * 8 + (threadIdx.x >> 5);
    int lane = threadIdx.x & 31;
    const float* x = g_Xf + (size_t)t * 256;
    float xv[8];
#pragma unroll
    for (int i = 0; i < 8; i++) xv[i] = x[lane + 32 * i];
    float best = 3.4e38f;
    int bi = NE;
#pragma unroll 1
    for (int c = 0; c < 32; c++) {
        int n = g_cand[(size_t)t * 32 + c];
        const float* cr = cb + (size_t)n * 256;
        float d = 0.f;
#pragma unroll
        for (int i = 0; i < 8; i++) d = fmaf(xv[i], cr[lane + 32 * i], d);
#pragma unroll
        for (int o = 16; o > 0; o >>= 1) d += __shfl_xor_sync(0xffffffffu, d, o);
        float sc = fmaf(-2.f, d, g_cnorm[n]);
        if (sc < best || (sc == best && n < bi)) { best = sc; bi = n; }
    }
    if (lane == 0) g_idx[t] = bi;
}

// ---------------- gather: out[b,e,h,w] = cb[idx[b,h,w], e] -------------------
__global__ void gather_kernel(const float* __restrict__ cb, float* __restrict__ out) {
    int bh = blockIdx.x;
    int b = bh >> 5, h = bh & 31;
    int w = threadIdx.x & 31, e0 = threadIdx.x >> 5;
    int t = b * 1024 + h * 32 + w;
    int idx = g_idx[t];
    const float* row = cb + (size_t)idx * 256;
    float* ob = out + (size_t)b * (256 * 1024) + h * 32 + w;
#pragma unroll
    for (int e = e0; e < 256; e += 8) ob[e * 1024] = row[e];
}

extern "C" void kernel_launch(void* const* d_in, const int* in_sizes, int n_in,
                              void* d_out, int out_size) {
    const float* z  = (const float*)d_in[0];
    const float* cb = (const float*)d_in[1];
    float* out = (float*)d_out;

    static int cfg_done = 0;
    if (!cfg_done) {
        cudaFuncSetAttribute(vq_gemm_kernel, cudaFuncAttributeMaxDynamicSharedMemorySize, SMEMT);
        cfg_done = 1;
    }

    conv_z_kernel<<<dim3(32, 8, 8), dim3(32, 8)>>>(z);
    conv_cb_kernel<<<NE / 8, 256>>>(cb);
    vq_gemm_kernel<<<1024, 256, SMEMT>>>();
    rescore_kernel<<<M_TOK / 8, 256>>>(cb);
    gather_kernel<<<256, 256>>>(cb, out);
}